// round 2
// baseline (speedup 1.0000x reference)
#include <cuda_runtime.h>
#include <cstddef>

#define N_USERS 200000
#define N_MOVIES 80000
#define NN 280000
#define HDIM 64
#define F_MOVIE 20
#define NE 1250000
#define NEL 500000

// Scratch (static device globals: allowed; runtime allocation is not).
// 16-byte aligned: float4 paths depend on it.
__device__ __align__(16) float g_X[(size_t)NN * HDIM];
__device__ __align__(16) float g_AGG[(size_t)NN * HDIM];
__device__ __align__(16) float g_Y[(size_t)NN * HDIM];
__device__ float g_DEG[NN];

// ---------------------------------------------------------------------------
// x_movie = movie_x @ lin_W.T + lin_b + movie_emb    (written into X rows
// [N_USERS, NN));  4 rows per 256-thread block.
// ---------------------------------------------------------------------------
__global__ void movie_init_kernel(const float* __restrict__ movie_x,
                                  const float* __restrict__ movie_emb,
                                  const float* __restrict__ lin_W,
                                  const float* __restrict__ lin_b,
                                  float* __restrict__ X) {
    __shared__ float sx[4][F_MOVIE];
    int lr  = threadIdx.x >> 6;           // local row 0..3
    int h   = threadIdx.x & 63;
    int row = blockIdx.x * 4 + lr;
    if (row < N_MOVIES && h < F_MOVIE)
        sx[lr][h] = movie_x[row * F_MOVIE + h];
    __syncthreads();
    if (row >= N_MOVIES) return;
    float acc = lin_b[h] + movie_emb[(size_t)row * HDIM + h];
#pragma unroll
    for (int f = 0; f < F_MOVIE; f++)
        acc += sx[lr][f] * lin_W[h * F_MOVIE + f];
    X[(size_t)(N_USERS + row) * HDIM + h] = acc;
}

// ---------------------------------------------------------------------------
// deg[dst] += 1 per edge    (edge_index is INT32: jax x64 is disabled)
// ---------------------------------------------------------------------------
__global__ void deg_kernel(const int* __restrict__ ei,
                           float* __restrict__ DEG) {
    int e = blockIdx.x * blockDim.x + threadIdx.x;
    if (e < NE) atomicAdd(&DEG[ei[NE + e]], 1.0f);
}

// ---------------------------------------------------------------------------
// AGG[dst] += X[src]  — one thread per (edge, float4-quarter): 16 threads/edge
// ---------------------------------------------------------------------------
__global__ void scatter_kernel(const int* __restrict__ ei,
                               const float* __restrict__ X,
                               float* __restrict__ AGG) {
    int idx = blockIdx.x * blockDim.x + threadIdx.x;   // over NE*16 = 20M
    if (idx >= NE * 16) return;
    int e = idx >> 4;
    int q = idx & 15;
    int src = __ldg(&ei[e]);
    int dst = __ldg(&ei[NE + e]);
    float4 v = *(const float4*)(X + (size_t)src * HDIM + q * 4);
    float* a = AGG + (size_t)dst * HDIM + q * 4;
    atomicAdd(a + 0, v.x);
    atomicAdd(a + 1, v.y);
    atomicAdd(a + 2, v.z);
    atomicAdd(a + 3, v.w);
}

// ---------------------------------------------------------------------------
// Y = act( (AGG/deg) @ Wl.T + bl + X @ Wr.T )
// Block: 256 threads, tile = 64 rows x 64 cols, per-thread 4x4 register tile.
// Dynamic smem: sWl[64][68] + sWr[64][68] (transposed: [k][h]) + sIn[64][132]
// (per row: [0..63]=mean, [64..127]=x).  Strides 68 / 132 avoid conflicts
// while keeping float4 alignment.
// ---------------------------------------------------------------------------
#define WPAD 68
#define IPAD 132
template <bool RELU>
__global__ void __launch_bounds__(256)
combine_kernel(const float* __restrict__ X, const float* __restrict__ AGG,
               const float* __restrict__ DEG,
               const float* __restrict__ Wl, const float* __restrict__ bl,
               const float* __restrict__ Wr, float* __restrict__ Y) {
    extern __shared__ float smem[];
    float* sWl = smem;                       // [64][WPAD], indexed [k][h]
    float* sWr = smem + 64 * WPAD;           // [64][WPAD]
    float* sIn = smem + 2 * 64 * WPAD;       // [64][IPAD]
    __shared__ float sInv[64];
    __shared__ float sb[64];

    int tid = threadIdx.x;
    // Transposed weight load: sW[k][h] = W[h*64+k]
    for (int i = tid; i < 64 * 64; i += 256) {
        int h = i >> 6, k = i & 63;
        sWl[k * WPAD + h] = Wl[i];
        sWr[k * WPAD + h] = Wr[i];
    }
    int base = blockIdx.x * 64;
    if (tid < 64) {
        sb[tid] = bl[tid];
        sInv[tid] = 1.0f / fmaxf(DEG[base + tid], 1.0f);
    }
    __syncthreads();

    // Input tile: coalesced loads, mean division fused
    for (int i = tid; i < 64 * 64; i += 256) {
        int r = i >> 6, k = i & 63;
        size_t g = (size_t)(base + r) * HDIM + k;
        sIn[r * IPAD + k]      = AGG[g] * sInv[r];
        sIn[r * IPAD + 64 + k] = X[g];
    }
    __syncthreads();

    int h0 = (tid & 15) * 4;
    int r0 = (tid >> 4) * 4;

    float acc[4][4];
#pragma unroll
    for (int i = 0; i < 4; i++)
#pragma unroll
        for (int j = 0; j < 4; j++) acc[i][j] = sb[h0 + j];

#pragma unroll
    for (int k = 0; k < 64; k += 4) {
        float4 wl[4], wr[4];
#pragma unroll
        for (int kk = 0; kk < 4; kk++) {
            wl[kk] = *(const float4*)&sWl[(k + kk) * WPAD + h0];
            wr[kk] = *(const float4*)&sWr[(k + kk) * WPAD + h0];
        }
#pragma unroll
        for (int i = 0; i < 4; i++) {
            float4 m4 = *(const float4*)&sIn[(r0 + i) * IPAD + k];
            float4 x4 = *(const float4*)&sIn[(r0 + i) * IPAD + 64 + k];
            float mv[4] = {m4.x, m4.y, m4.z, m4.w};
            float xv[4] = {x4.x, x4.y, x4.z, x4.w};
#pragma unroll
            for (int kk = 0; kk < 4; kk++) {
                acc[i][0] += mv[kk] * wl[kk].x + xv[kk] * wr[kk].x;
                acc[i][1] += mv[kk] * wl[kk].y + xv[kk] * wr[kk].y;
                acc[i][2] += mv[kk] * wl[kk].z + xv[kk] * wr[kk].z;
                acc[i][3] += mv[kk] * wl[kk].w + xv[kk] * wr[kk].w;
            }
        }
    }

#pragma unroll
    for (int i = 0; i < 4; i++) {
        float4 o;
        o.x = acc[i][0]; o.y = acc[i][1]; o.z = acc[i][2]; o.w = acc[i][3];
        if (RELU) {
            o.x = fmaxf(o.x, 0.f); o.y = fmaxf(o.y, 0.f);
            o.z = fmaxf(o.z, 0.f); o.w = fmaxf(o.w, 0.f);
        }
        *(float4*)&Y[(size_t)(base + r0 + i) * HDIM + h0] = o;
    }
}

// ---------------------------------------------------------------------------
// out[e] = dot(Y[u[e]], Y[N_USERS + m[e]])  — warp per label edge
// ---------------------------------------------------------------------------
__global__ void dot_kernel(const int* __restrict__ eli,
                           const float* __restrict__ Y,
                           float* __restrict__ out) {
    int gw   = (blockIdx.x * blockDim.x + threadIdx.x) >> 5;
    int lane = threadIdx.x & 31;
    if (gw >= NEL) return;
    int u = __ldg(&eli[gw]);
    int m = __ldg(&eli[NEL + gw]);
    const float* pu = Y + (size_t)u * HDIM;
    const float* pm = Y + (size_t)(N_USERS + m) * HDIM;
    float s = pu[lane] * pm[lane] + pu[lane + 32] * pm[lane + 32];
#pragma unroll
    for (int o = 16; o; o >>= 1) s += __shfl_xor_sync(0xffffffffu, s, o);
    if (lane == 0) out[gw] = s;
}

// ---------------------------------------------------------------------------
extern "C" void kernel_launch(void* const* d_in, const int* in_sizes, int n_in,
                              void* d_out, int out_size) {
    const float* movie_x   = (const float*)d_in[0];
    const float* user_emb  = (const float*)d_in[1];
    const float* movie_emb = (const float*)d_in[2];
    const float* lin_W     = (const float*)d_in[3];
    const float* lin_b     = (const float*)d_in[4];
    const float* W1l       = (const float*)d_in[5];
    const float* b1        = (const float*)d_in[6];
    const float* W1r       = (const float*)d_in[7];
    const float* W2l       = (const float*)d_in[8];
    const float* b2        = (const float*)d_in[9];
    const float* W2r       = (const float*)d_in[10];
    const int*   ei        = (const int*)d_in[11];   // int32: jax x64 disabled
    const int*   eli       = (const int*)d_in[12];   // int32
    float* out = (float*)d_out;

    float *dX, *dAGG, *dY, *dDEG;
    cudaGetSymbolAddress((void**)&dX,   g_X);
    cudaGetSymbolAddress((void**)&dAGG, g_AGG);
    cudaGetSymbolAddress((void**)&dY,   g_Y);
    cudaGetSymbolAddress((void**)&dDEG, g_DEG);

    const size_t smemC = (size_t)(2 * 64 * WPAD + 64 * IPAD) * sizeof(float);
    cudaFuncSetAttribute(combine_kernel<true>,
                         cudaFuncAttributeMaxDynamicSharedMemorySize, (int)smemC);
    cudaFuncSetAttribute(combine_kernel<false>,
                         cudaFuncAttributeMaxDynamicSharedMemorySize, (int)smemC);

    // ---- node features ----
    cudaMemsetAsync(dDEG, 0, NN * sizeof(float));
    cudaMemsetAsync(dAGG, 0, (size_t)NN * HDIM * sizeof(float));
    cudaMemcpyAsync(dX, user_emb, (size_t)N_USERS * HDIM * sizeof(float),
                    cudaMemcpyDeviceToDevice);
    movie_init_kernel<<<N_MOVIES / 4, 256>>>(movie_x, movie_emb, lin_W, lin_b, dX);
    deg_kernel<<<(NE + 255) / 256, 256>>>(ei, dDEG);

    // ---- layer 1 ----
    scatter_kernel<<<NE * 16 / 256, 256>>>(ei, dX, dAGG);
    combine_kernel<true><<<NN / 64, 256, smemC>>>(dX, dAGG, dDEG, W1l, b1, W1r, dY);

    // ---- layer 2 ----
    cudaMemsetAsync(dAGG, 0, (size_t)NN * HDIM * sizeof(float));
    scatter_kernel<<<NE * 16 / 256, 256>>>(ei, dY, dAGG);
    combine_kernel<false><<<NN / 64, 256, smemC>>>(dY, dAGG, dDEG, W2l, b2, W2r, dX);

    // ---- decode ----
    dot_kernel<<<(NEL * 32) / 256, 256>>>(eli, dX, out);
}

// round 3
// speedup vs baseline: 1.4348x; 1.4348x over previous
#include <cuda_runtime.h>
#include <cstddef>

#define N_USERS 200000
#define N_MOVIES 80000
#define NN 280000
#define HDIM 64
#define F_MOVIE 20
#define NE 1250000
#define NEL 500000

typedef unsigned long long u64;

// Scratch (static device globals: allowed; runtime allocation is not).
__device__ __align__(16) float g_X[(size_t)NN * HDIM];
__device__ __align__(16) float g_AGG[(size_t)NN * HDIM];
__device__ __align__(16) float g_Y[(size_t)NN * HDIM];
__device__ float g_DEG[NN];

// ---- packed f32x2 helpers (Blackwell FFMA2 path, PTX-only) -----------------
__device__ __forceinline__ u64 pack2(float lo, float hi) {
    u64 r; asm("mov.b64 %0, {%1, %2};" : "=l"(r) : "f"(lo), "f"(hi)); return r;
}
__device__ __forceinline__ u64 bcast2(float x) {
    u64 r; asm("mov.b64 %0, {%1, %1};" : "=l"(r) : "f"(x)); return r;
}
__device__ __forceinline__ u64 ffma2(u64 a, u64 b, u64 c) {
    u64 d; asm("fma.rn.f32x2 %0, %1, %2, %3;" : "=l"(d) : "l"(a), "l"(b), "l"(c));
    return d;
}
__device__ __forceinline__ float2 unpack2(u64 v) {
    float2 f; asm("mov.b64 {%0, %1}, %2;" : "=f"(f.x), "=f"(f.y) : "l"(v)); return f;
}

// ---------------------------------------------------------------------------
// x_movie = movie_x @ lin_W.T + lin_b + movie_emb
// ---------------------------------------------------------------------------
__global__ void movie_init_kernel(const float* __restrict__ movie_x,
                                  const float* __restrict__ movie_emb,
                                  const float* __restrict__ lin_W,
                                  const float* __restrict__ lin_b,
                                  float* __restrict__ X) {
    __shared__ float sx[4][F_MOVIE];
    int lr  = threadIdx.x >> 6;
    int h   = threadIdx.x & 63;
    int row = blockIdx.x * 4 + lr;
    if (row < N_MOVIES && h < F_MOVIE)
        sx[lr][h] = movie_x[row * F_MOVIE + h];
    __syncthreads();
    if (row >= N_MOVIES) return;
    float acc = lin_b[h] + movie_emb[(size_t)row * HDIM + h];
#pragma unroll
    for (int f = 0; f < F_MOVIE; f++)
        acc += sx[lr][f] * lin_W[h * F_MOVIE + f];
    X[(size_t)(N_USERS + row) * HDIM + h] = acc;
}

// ---------------------------------------------------------------------------
// deg[dst] += 1 per edge    (edge_index is INT32)
// ---------------------------------------------------------------------------
__global__ void deg_kernel(const int* __restrict__ ei,
                           float* __restrict__ DEG) {
    int e = blockIdx.x * blockDim.x + threadIdx.x;
    if (e < NE) atomicAdd(&DEG[ei[NE + e]], 1.0f);
}

// ---------------------------------------------------------------------------
// AGG[dst] += X[src] — 16 threads/edge, one red.global.add.v4.f32 each
// (4x fewer L2 atomic messages than scalar atomicAdd)
// ---------------------------------------------------------------------------
__global__ void scatter_kernel(const int* __restrict__ ei,
                               const float* __restrict__ X,
                               float* __restrict__ AGG) {
    int idx = blockIdx.x * blockDim.x + threadIdx.x;   // over NE*16
    if (idx >= NE * 16) return;
    int e = idx >> 4;
    int q = idx & 15;
    int src = __ldg(&ei[e]);
    int dst = __ldg(&ei[NE + e]);
    float4 v = *(const float4*)(X + (size_t)src * HDIM + q * 4);
    float* a = AGG + (size_t)dst * HDIM + q * 4;
    asm volatile("red.global.add.v4.f32 [%0], {%1, %2, %3, %4};"
                 :: "l"(a), "f"(v.x), "f"(v.y), "f"(v.z), "f"(v.w)
                 : "memory");
}

// ---------------------------------------------------------------------------
// Y = act( (AGG/deg) @ Wl.T + bl + X @ Wr.T )
// 256 threads, tile = 128 rows x 64 cols, thread tile 8x4, packed f32x2 FFMA2.
// smem: sWl/sWr [64][WPAD] ([k][h], transposed), sIn [128][IPAD]
// ([r][0:64]=mean, [64:128]=x). 100 KB dynamic -> 2 blocks/SM.
// ---------------------------------------------------------------------------
#define WPAD 68
#define IPAD 132
#define RPB  128
template <bool RELU>
__global__ void __launch_bounds__(256, 2)
combine_kernel(const float* __restrict__ X, const float* __restrict__ AGG,
               const float* __restrict__ DEG,
               const float* __restrict__ Wl, const float* __restrict__ bl,
               const float* __restrict__ Wr, float* __restrict__ Y) {
    extern __shared__ float smem[];
    float* sWl = smem;                       // [64][WPAD]
    float* sWr = smem + 64 * WPAD;           // [64][WPAD]
    float* sIn = smem + 2 * 64 * WPAD;       // [128][IPAD]
    __shared__ float sInv[RPB];
    __shared__ float sb[64];

    int tid = threadIdx.x;
    for (int i = tid; i < 64 * 64; i += 256) {
        int h = i >> 6, k = i & 63;
        sWl[k * WPAD + h] = Wl[i];
        sWr[k * WPAD + h] = Wr[i];
    }
    int base = blockIdx.x * RPB;
    if (tid < 64) sb[tid] = bl[tid];
    if (tid < RPB) {
        int row = base + tid;
        sInv[tid] = (row < NN) ? 1.0f / fmaxf(DEG[row], 1.0f) : 0.0f;
    }
    __syncthreads();

    // Input tile: coalesced global loads, conflict-free STS, mean fused
    for (int i = tid; i < RPB * 64; i += 256) {
        int r = i >> 6, k = i & 63;
        int row = base + r;
        float a = 0.f, xv = 0.f;
        if (row < NN) {
            size_t g = (size_t)row * HDIM + k;
            a  = AGG[g] * sInv[r];
            xv = X[g];
        }
        sIn[r * IPAD + k]      = a;
        sIn[r * IPAD + 64 + k] = xv;
    }
    __syncthreads();

    int h0 = (tid & 15) * 4;
    int r0 = (tid >> 4) * 8;

    u64 acc[8][2];
    {
        u64 b01 = pack2(sb[h0], sb[h0 + 1]);
        u64 b23 = pack2(sb[h0 + 2], sb[h0 + 3]);
#pragma unroll
        for (int i = 0; i < 8; i++) { acc[i][0] = b01; acc[i][1] = b23; }
    }

#pragma unroll
    for (int k = 0; k < 64; k += 4) {
        ulonglong2 wl[4], wr[4];   // LDS.128 -> two aligned f32x2 pairs each
#pragma unroll
        for (int kk = 0; kk < 4; kk++) {
            wl[kk] = *(const ulonglong2*)&sWl[(k + kk) * WPAD + h0];
            wr[kk] = *(const ulonglong2*)&sWr[(k + kk) * WPAD + h0];
        }
#pragma unroll
        for (int i = 0; i < 8; i++) {
            float4 m4 = *(const float4*)&sIn[(r0 + i) * IPAD + k];
            float4 x4 = *(const float4*)&sIn[(r0 + i) * IPAD + 64 + k];
            u64 t;
            t = bcast2(m4.x); acc[i][0] = ffma2(t, wl[0].x, acc[i][0]);
                              acc[i][1] = ffma2(t, wl[0].y, acc[i][1]);
            t = bcast2(x4.x); acc[i][0] = ffma2(t, wr[0].x, acc[i][0]);
                              acc[i][1] = ffma2(t, wr[0].y, acc[i][1]);
            t = bcast2(m4.y); acc[i][0] = ffma2(t, wl[1].x, acc[i][0]);
                              acc[i][1] = ffma2(t, wl[1].y, acc[i][1]);
            t = bcast2(x4.y); acc[i][0] = ffma2(t, wr[1].x, acc[i][0]);
                              acc[i][1] = ffma2(t, wr[1].y, acc[i][1]);
            t = bcast2(m4.z); acc[i][0] = ffma2(t, wl[2].x, acc[i][0]);
                              acc[i][1] = ffma2(t, wl[2].y, acc[i][1]);
            t = bcast2(x4.z); acc[i][0] = ffma2(t, wr[2].x, acc[i][0]);
                              acc[i][1] = ffma2(t, wr[2].y, acc[i][1]);
            t = bcast2(m4.w); acc[i][0] = ffma2(t, wl[3].x, acc[i][0]);
                              acc[i][1] = ffma2(t, wl[3].y, acc[i][1]);
            t = bcast2(x4.w); acc[i][0] = ffma2(t, wr[3].x, acc[i][0]);
                              acc[i][1] = ffma2(t, wr[3].y, acc[i][1]);
        }
    }

#pragma unroll
    for (int i = 0; i < 8; i++) {
        int row = base + r0 + i;
        if (row >= NN) break;
        float2 lo = unpack2(acc[i][0]);
        float2 hi = unpack2(acc[i][1]);
        float4 o;
        o.x = lo.x; o.y = lo.y; o.z = hi.x; o.w = hi.y;
        if (RELU) {
            o.x = fmaxf(o.x, 0.f); o.y = fmaxf(o.y, 0.f);
            o.z = fmaxf(o.z, 0.f); o.w = fmaxf(o.w, 0.f);
        }
        *(float4*)&Y[(size_t)row * HDIM + h0] = o;
    }
}

// ---------------------------------------------------------------------------
// out[e] = dot(Y[u[e]], Y[N_USERS + m[e]]) — warp per label edge
// ---------------------------------------------------------------------------
__global__ void dot_kernel(const int* __restrict__ eli,
                           const float* __restrict__ Y,
                           float* __restrict__ out) {
    int gw   = (blockIdx.x * blockDim.x + threadIdx.x) >> 5;
    int lane = threadIdx.x & 31;
    if (gw >= NEL) return;
    int u = __ldg(&eli[gw]);
    int m = __ldg(&eli[NEL + gw]);
    const float* pu = Y + (size_t)u * HDIM;
    const float* pm = Y + (size_t)(N_USERS + m) * HDIM;
    float s = pu[lane] * pm[lane] + pu[lane + 32] * pm[lane + 32];
#pragma unroll
    for (int o = 16; o; o >>= 1) s += __shfl_xor_sync(0xffffffffu, s, o);
    if (lane == 0) out[gw] = s;
}

// ---------------------------------------------------------------------------
extern "C" void kernel_launch(void* const* d_in, const int* in_sizes, int n_in,
                              void* d_out, int out_size) {
    const float* movie_x   = (const float*)d_in[0];
    const float* user_emb  = (const float*)d_in[1];
    const float* movie_emb = (const float*)d_in[2];
    const float* lin_W     = (const float*)d_in[3];
    const float* lin_b     = (const float*)d_in[4];
    const float* W1l       = (const float*)d_in[5];
    const float* b1        = (const float*)d_in[6];
    const float* W1r       = (const float*)d_in[7];
    const float* W2l       = (const float*)d_in[8];
    const float* b2        = (const float*)d_in[9];
    const float* W2r       = (const float*)d_in[10];
    const int*   ei        = (const int*)d_in[11];
    const int*   eli       = (const int*)d_in[12];
    float* out = (float*)d_out;

    float *dX, *dAGG, *dY, *dDEG;
    cudaGetSymbolAddress((void**)&dX,   g_X);
    cudaGetSymbolAddress((void**)&dAGG, g_AGG);
    cudaGetSymbolAddress((void**)&dY,   g_Y);
    cudaGetSymbolAddress((void**)&dDEG, g_DEG);

    const size_t smemC = (size_t)(2 * 64 * WPAD + RPB * IPAD) * sizeof(float);
    cudaFuncSetAttribute(combine_kernel<true>,
                         cudaFuncAttributeMaxDynamicSharedMemorySize, (int)smemC);
    cudaFuncSetAttribute(combine_kernel<false>,
                         cudaFuncAttributeMaxDynamicSharedMemorySize, (int)smemC);

    const int gridC = (NN + RPB - 1) / RPB;   // 2188

    // ---- node features ----
    cudaMemsetAsync(dDEG, 0, NN * sizeof(float));
    cudaMemsetAsync(dAGG, 0, (size_t)NN * HDIM * sizeof(float));
    cudaMemcpyAsync(dX, user_emb, (size_t)N_USERS * HDIM * sizeof(float),
                    cudaMemcpyDeviceToDevice);
    movie_init_kernel<<<N_MOVIES / 4, 256>>>(movie_x, movie_emb, lin_W, lin_b, dX);
    deg_kernel<<<(NE + 255) / 256, 256>>>(ei, dDEG);

    // ---- layer 1 ----
    scatter_kernel<<<NE * 16 / 256, 256>>>(ei, dX, dAGG);
    combine_kernel<true><<<gridC, 256, smemC>>>(dX, dAGG, dDEG, W1l, b1, W1r, dY);

    // ---- layer 2 ----
    cudaMemsetAsync(dAGG, 0, (size_t)NN * HDIM * sizeof(float));
    scatter_kernel<<<NE * 16 / 256, 256>>>(ei, dY, dAGG);
    combine_kernel<false><<<gridC, 256, smemC>>>(dY, dAGG, dDEG, W2l, b2, W2r, dX);

    // ---- decode ----
    dot_kernel<<<(NEL * 32) / 256, 256>>>(eli, dX, out);
}

// round 4
// speedup vs baseline: 1.5905x; 1.1085x over previous
#include <cuda_runtime.h>
#include <cstddef>

#define N_USERS 200000
#define N_MOVIES 80000
#define NN 280000
#define HDIM 64
#define F_MOVIE 20
#define NE 1250000
#define NEL 500000

typedef unsigned long long u64;

// Scratch (static device globals: allowed; runtime allocation is not).
__device__ __align__(16) float g_X[(size_t)NN * HDIM];
__device__ __align__(16) float g_AGG[(size_t)NN * HDIM];
__device__ __align__(16) float g_Y[(size_t)NN * HDIM];
__device__ float g_DEG[NN];

// ---- packed f32x2 helpers (Blackwell FFMA2 path, PTX-only) -----------------
__device__ __forceinline__ u64 pack2(float lo, float hi) {
    u64 r; asm("mov.b64 %0, {%1, %2};" : "=l"(r) : "f"(lo), "f"(hi)); return r;
}
__device__ __forceinline__ u64 bcast2(float x) {
    u64 r; asm("mov.b64 %0, {%1, %1};" : "=l"(r) : "f"(x)); return r;
}
__device__ __forceinline__ u64 ffma2(u64 a, u64 b, u64 c) {
    u64 d; asm("fma.rn.f32x2 %0, %1, %2, %3;" : "=l"(d) : "l"(a), "l"(b), "l"(c));
    return d;
}
__device__ __forceinline__ float2 unpack2(u64 v) {
    float2 f; asm("mov.b64 {%0, %1}, %2;" : "=f"(f.x), "=f"(f.y) : "l"(v)); return f;
}

// ---------------------------------------------------------------------------
// x_movie = movie_x @ lin_W.T + lin_b + movie_emb
// ---------------------------------------------------------------------------
__global__ void movie_init_kernel(const float* __restrict__ movie_x,
                                  const float* __restrict__ movie_emb,
                                  const float* __restrict__ lin_W,
                                  const float* __restrict__ lin_b,
                                  float* __restrict__ X) {
    __shared__ float sx[4][F_MOVIE];
    int lr  = threadIdx.x >> 6;
    int h   = threadIdx.x & 63;
    int row = blockIdx.x * 4 + lr;
    if (row < N_MOVIES && h < F_MOVIE)
        sx[lr][h] = movie_x[row * F_MOVIE + h];
    __syncthreads();
    if (row >= N_MOVIES) return;
    float acc = lin_b[h] + movie_emb[(size_t)row * HDIM + h];
#pragma unroll
    for (int f = 0; f < F_MOVIE; f++)
        acc += sx[lr][f] * lin_W[h * F_MOVIE + f];
    X[(size_t)(N_USERS + row) * HDIM + h] = acc;
}

// ---------------------------------------------------------------------------
// deg[dst] += 1 per edge    (edge_index is INT32)
// ---------------------------------------------------------------------------
__global__ void deg_kernel(const int* __restrict__ ei,
                           float* __restrict__ DEG) {
    int e = blockIdx.x * blockDim.x + threadIdx.x;
    if (e < NE) atomicAdd(&DEG[ei[NE + e]], 1.0f);
}

// ---------------------------------------------------------------------------
// AGG[dst] += X[src] — 16 threads/edge, one red.global.add.v4.f32 each
// ---------------------------------------------------------------------------
__global__ void scatter_kernel(const int* __restrict__ ei,
                               const float* __restrict__ X,
                               float* __restrict__ AGG) {
    int idx = blockIdx.x * blockDim.x + threadIdx.x;   // over NE*16
    if (idx >= NE * 16) return;
    int e = idx >> 4;
    int q = idx & 15;
    int src = __ldg(&ei[e]);
    int dst = __ldg(&ei[NE + e]);
    float4 v = *(const float4*)(X + (size_t)src * HDIM + q * 4);
    float* a = AGG + (size_t)dst * HDIM + q * 4;
    asm volatile("red.global.add.v4.f32 [%0], {%1, %2, %3, %4};"
                 :: "l"(a), "f"(v.x), "f"(v.y), "f"(v.z), "f"(v.w)
                 : "memory");
}

// ---------------------------------------------------------------------------
// Y = act( (AGG/deg) @ Wl.T + bl + X @ Wr.T )   — PHASED version.
// Phase 1: sW=Wl^T, sIn=mean tile; accumulate.  Phase 2: sW=Wr^T, sIn=x tile;
// accumulate + epilogue.  One weight buffer + one input buffer -> 52.2 KB
// dynamic smem -> 3 blocks/SM (24 warps) vs previous 2 (16 warps).
// 256 threads, 128 rows x 64 cols per block, 8x4 thread tile, FFMA2.
// ---------------------------------------------------------------------------
#define WPAD 68
#define RPB  128

__device__ __forceinline__ void accum_phase(const float* __restrict__ sW,
                                            const float* __restrict__ sIn,
                                            int h0, int r0, u64 acc[8][2]) {
#pragma unroll
    for (int k = 0; k < 64; k += 4) {
        ulonglong2 w[4];   // LDS.128 -> two aligned f32x2 pairs each
#pragma unroll
        for (int kk = 0; kk < 4; kk++)
            w[kk] = *(const ulonglong2*)&sW[(k + kk) * WPAD + h0];
#pragma unroll
        for (int i = 0; i < 8; i++) {
            float4 v = *(const float4*)&sIn[(r0 + i) * WPAD + k];
            u64 t;
            t = bcast2(v.x); acc[i][0] = ffma2(t, w[0].x, acc[i][0]);
                             acc[i][1] = ffma2(t, w[0].y, acc[i][1]);
            t = bcast2(v.y); acc[i][0] = ffma2(t, w[1].x, acc[i][0]);
                             acc[i][1] = ffma2(t, w[1].y, acc[i][1]);
            t = bcast2(v.z); acc[i][0] = ffma2(t, w[2].x, acc[i][0]);
                             acc[i][1] = ffma2(t, w[2].y, acc[i][1]);
            t = bcast2(v.w); acc[i][0] = ffma2(t, w[3].x, acc[i][0]);
                             acc[i][1] = ffma2(t, w[3].y, acc[i][1]);
        }
    }
}

template <bool RELU, bool ZEROAGG>
__global__ void __launch_bounds__(256, 3)
combine_kernel(const float* __restrict__ X, float* __restrict__ AGG,
               const float* __restrict__ DEG,
               const float* __restrict__ Wl, const float* __restrict__ bl,
               const float* __restrict__ Wr, float* __restrict__ Y) {
    extern __shared__ float smem[];
    float* sW  = smem;               // [64][WPAD]   (17.4 KB)
    float* sIn = smem + 64 * WPAD;   // [128][WPAD]  (34.8 KB)
    __shared__ float sInv[RPB];
    __shared__ float sb[64];

    int tid  = threadIdx.x;
    int base = blockIdx.x * RPB;

    // ---- phase 1 loads: Wl^T, bias, 1/deg ----
    for (int i = tid; i < 64 * 64; i += 256) {
        int h = i >> 6, k = i & 63;
        sW[k * WPAD + h] = Wl[i];
    }
    if (tid < 64) sb[tid] = bl[tid];
    if (tid < RPB) {
        int row = base + tid;
        sInv[tid] = (row < NN) ? 1.0f / fmaxf(DEG[row], 1.0f) : 0.0f;
    }
    __syncthreads();

    // mean tile (float4, coalesced)
    for (int i = tid; i < RPB * 16; i += 256) {
        int r = i >> 4, k4 = (i & 15) * 4;
        int row = base + r;
        float4 v = make_float4(0.f, 0.f, 0.f, 0.f);
        if (row < NN) {
            v = *(const float4*)&AGG[(size_t)row * HDIM + k4];
            float s = sInv[r];
            v.x *= s; v.y *= s; v.z *= s; v.w *= s;
        }
        *(float4*)&sIn[r * WPAD + k4] = v;
    }
    __syncthreads();

    int h0 = (tid & 15) * 4;
    int r0 = (tid >> 4) * 8;

    u64 acc[8][2];
    {
        u64 b01 = pack2(sb[h0], sb[h0 + 1]);
        u64 b23 = pack2(sb[h0 + 2], sb[h0 + 3]);
#pragma unroll
        for (int i = 0; i < 8; i++) { acc[i][0] = b01; acc[i][1] = b23; }
    }

    accum_phase(sW, sIn, h0, r0, acc);      // mean @ Wl^T
    __syncthreads();                         // protect smem before reuse

    // ---- phase 2 loads: Wr^T + x tile (+ zero AGG for next layer) ----
    for (int i = tid; i < 64 * 64; i += 256) {
        int h = i >> 6, k = i & 63;
        sW[k * WPAD + h] = Wr[i];
    }
    for (int i = tid; i < RPB * 16; i += 256) {
        int r = i >> 4, k4 = (i & 15) * 4;
        int row = base + r;
        float4 v = make_float4(0.f, 0.f, 0.f, 0.f);
        if (row < NN) {
            size_t g = (size_t)row * HDIM + k4;
            v = *(const float4*)&X[g];
            if (ZEROAGG) *(float4*)&AGG[g] = make_float4(0.f, 0.f, 0.f, 0.f);
        }
        *(float4*)&sIn[r * WPAD + k4] = v;
    }
    __syncthreads();

    accum_phase(sW, sIn, h0, r0, acc);      // + x @ Wr^T

    // ---- epilogue ----
#pragma unroll
    for (int i = 0; i < 8; i++) {
        int row = base + r0 + i;
        if (row >= NN) break;
        float2 lo = unpack2(acc[i][0]);
        float2 hi = unpack2(acc[i][1]);
        float4 o;
        o.x = lo.x; o.y = lo.y; o.z = hi.x; o.w = hi.y;
        if (RELU) {
            o.x = fmaxf(o.x, 0.f); o.y = fmaxf(o.y, 0.f);
            o.z = fmaxf(o.z, 0.f); o.w = fmaxf(o.w, 0.f);
        }
        *(float4*)&Y[(size_t)row * HDIM + h0] = o;
    }
}

// ---------------------------------------------------------------------------
// out[e] = dot(Y[u[e]], Y[N_USERS + m[e]]) — 16 lanes per label edge, float4
// ---------------------------------------------------------------------------
__global__ void dot_kernel(const int* __restrict__ eli,
                           const float* __restrict__ Y,
                           float* __restrict__ out) {
    int gw = (blockIdx.x * blockDim.x + threadIdx.x) >> 4;
    int l  = threadIdx.x & 15;
    if (gw >= NEL) return;
    int u = __ldg(&eli[gw]);
    int m = __ldg(&eli[NEL + gw]);
    float4 a = *(const float4*)&Y[(size_t)u * HDIM + l * 4];
    float4 b = *(const float4*)&Y[(size_t)(N_USERS + m) * HDIM + l * 4];
    float s = a.x * b.x + a.y * b.y + a.z * b.z + a.w * b.w;
#pragma unroll
    for (int o = 8; o; o >>= 1) s += __shfl_xor_sync(0xffffffffu, s, o);
    if (l == 0) out[gw] = s;
}

// ---------------------------------------------------------------------------
extern "C" void kernel_launch(void* const* d_in, const int* in_sizes, int n_in,
                              void* d_out, int out_size) {
    const float* movie_x   = (const float*)d_in[0];
    const float* user_emb  = (const float*)d_in[1];
    const float* movie_emb = (const float*)d_in[2];
    const float* lin_W     = (const float*)d_in[3];
    const float* lin_b     = (const float*)d_in[4];
    const float* W1l       = (const float*)d_in[5];
    const float* b1        = (const float*)d_in[6];
    const float* W1r       = (const float*)d_in[7];
    const float* W2l       = (const float*)d_in[8];
    const float* b2        = (const float*)d_in[9];
    const float* W2r       = (const float*)d_in[10];
    const int*   ei        = (const int*)d_in[11];
    const int*   eli       = (const int*)d_in[12];
    float* out = (float*)d_out;

    float *dX, *dAGG, *dY, *dDEG;
    cudaGetSymbolAddress((void**)&dX,   g_X);
    cudaGetSymbolAddress((void**)&dAGG, g_AGG);
    cudaGetSymbolAddress((void**)&dY,   g_Y);
    cudaGetSymbolAddress((void**)&dDEG, g_DEG);

    const size_t smemC = (size_t)((64 + RPB) * WPAD) * sizeof(float); // 52.2 KB
    cudaFuncSetAttribute(combine_kernel<true, true>,
                         cudaFuncAttributeMaxDynamicSharedMemorySize, (int)smemC);
    cudaFuncSetAttribute(combine_kernel<false, false>,
                         cudaFuncAttributeMaxDynamicSharedMemorySize, (int)smemC);

    const int gridC = (NN + RPB - 1) / RPB;   // 2188

    // ---- node features ----
    cudaMemsetAsync(dDEG, 0, NN * sizeof(float));
    cudaMemsetAsync(dAGG, 0, (size_t)NN * HDIM * sizeof(float));
    cudaMemcpyAsync(dX, user_emb, (size_t)N_USERS * HDIM * sizeof(float),
                    cudaMemcpyDeviceToDevice);
    movie_init_kernel<<<N_MOVIES / 4, 256>>>(movie_x, movie_emb, lin_W, lin_b, dX);
    deg_kernel<<<(NE + 255) / 256, 256>>>(ei, dDEG);

    // ---- layer 1 ----
    scatter_kernel<<<NE * 16 / 256, 256>>>(ei, dX, dAGG);
    combine_kernel<true, true><<<gridC, 256, smemC>>>(dX, dAGG, dDEG,
                                                      W1l, b1, W1r, dY);

    // ---- layer 2 (AGG already zeroed by combine<true,true>) ----
    scatter_kernel<<<NE * 16 / 256, 256>>>(ei, dY, dAGG);
    combine_kernel<false, false><<<gridC, 256, smemC>>>(dY, dAGG, dDEG,
                                                        W2l, b2, W2r, dX);

    // ---- decode ----
    dot_kernel<<<(NEL * 16) / 256, 256>>>(eli, dX, out);
}

// round 5
// speedup vs baseline: 1.7579x; 1.1052x over previous
#include <cuda_runtime.h>
#include <cstddef>

#define N_USERS 200000
#define N_MOVIES 80000
#define NN 280000
#define HDIM 64
#define F_MOVIE 20
#define NE 1250000
#define NEL 500000
#define NB 274            // ceil(NN / 1024)

typedef unsigned long long u64;

// Scratch (static device globals: allowed; runtime allocation is not).
__device__ __align__(16) float g_X[(size_t)NN * HDIM];
__device__ __align__(16) float g_Y[(size_t)NN * HDIM];
__device__ __align__(16) float g_Z[(size_t)NN * HDIM];
__device__ int g_DEGI[NN];
__device__ int g_OFF[NN + 1];
__device__ int g_CUR[NN];
__device__ int g_BSUM[512];
__device__ int g_CSR[NE];

// ---- packed f32x2 helpers (Blackwell FFMA2 path, PTX-only) -----------------
__device__ __forceinline__ u64 pack2(float lo, float hi) {
    u64 r; asm("mov.b64 %0, {%1, %2};" : "=l"(r) : "f"(lo), "f"(hi)); return r;
}
__device__ __forceinline__ u64 bcast2(float x) {
    u64 r; asm("mov.b64 %0, {%1, %1};" : "=l"(r) : "f"(x)); return r;
}
__device__ __forceinline__ u64 ffma2(u64 a, u64 b, u64 c) {
    u64 d; asm("fma.rn.f32x2 %0, %1, %2, %3;" : "=l"(d) : "l"(a), "l"(b), "l"(c));
    return d;
}
__device__ __forceinline__ float2 unpack2(u64 v) {
    float2 f; asm("mov.b64 {%0, %1}, %2;" : "=f"(f.x), "=f"(f.y) : "l"(v)); return f;
}

// ---------------------------------------------------------------------------
// X init: users = copy user_emb; movies = movie_x @ lin_W.T + lin_b + movie_emb
// 4 rows per 256-thread block, over all NN rows.
// ---------------------------------------------------------------------------
__global__ void init_X_kernel(const float* __restrict__ movie_x,
                              const float* __restrict__ user_emb,
                              const float* __restrict__ movie_emb,
                              const float* __restrict__ lin_W,
                              const float* __restrict__ lin_b,
                              float* __restrict__ X) {
    __shared__ float sx[4][F_MOVIE];
    int lr  = threadIdx.x >> 6;
    int h   = threadIdx.x & 63;
    int row = blockIdx.x * 4 + lr;
    int mrow = row - N_USERS;
    if (row < NN && mrow >= 0 && h < F_MOVIE)
        sx[lr][h] = movie_x[mrow * F_MOVIE + h];
    __syncthreads();
    if (row >= NN) return;
    if (mrow < 0) {
        X[(size_t)row * HDIM + h] = user_emb[(size_t)row * HDIM + h];
    } else {
        float acc = lin_b[h] + movie_emb[(size_t)mrow * HDIM + h];
#pragma unroll
        for (int f = 0; f < F_MOVIE; f++)
            acc += sx[lr][f] * lin_W[h * F_MOVIE + f];
        X[(size_t)row * HDIM + h] = acc;
    }
}

// ---------------------------------------------------------------------------
// CSR build: histogram -> block sums -> scan of sums -> local scan -> fill
// ---------------------------------------------------------------------------
__global__ void hist_kernel(const int* __restrict__ ei, int* __restrict__ degi) {
    int e = blockIdx.x * blockDim.x + threadIdx.x;
    if (e < NE) atomicAdd(&degi[ei[NE + e]], 1);
}

__global__ void scanA_kernel(const int* __restrict__ degi, int* __restrict__ bsum) {
    __shared__ int ws[8];
    int b = blockIdx.x, t = threadIdx.x;
    int i0 = b * 1024 + t * 4;
    int s = 0;
#pragma unroll
    for (int j = 0; j < 4; j++) { int i = i0 + j; s += (i < NN) ? degi[i] : 0; }
#pragma unroll
    for (int o = 16; o; o >>= 1) s += __shfl_xor_sync(0xffffffffu, s, o);
    if ((t & 31) == 0) ws[t >> 5] = s;
    __syncthreads();
    if (t == 0) {
        int tot = 0;
#pragma unroll
        for (int w = 0; w < 8; w++) tot += ws[w];
        bsum[b] = tot;
    }
}

__global__ void scanB_kernel(int* __restrict__ bsum, int* __restrict__ off) {
    __shared__ int s[512];
    int t = threadIdx.x;
    s[t] = (t < NB) ? bsum[t] : 0;
    __syncthreads();
#pragma unroll
    for (int o = 1; o < 512; o <<= 1) {
        int x = (t >= o) ? s[t - o] : 0;
        __syncthreads();
        s[t] += x;
        __syncthreads();
    }
    int excl = (t == 0) ? 0 : s[t - 1];
    if (t < NB) bsum[t] = excl;
    if (t == 0) off[NN] = NE;
}

__global__ void scanC_kernel(const int* __restrict__ degi,
                             const int* __restrict__ boff,
                             int* __restrict__ off, int* __restrict__ cur) {
    __shared__ int ss[256];
    int b = blockIdx.x, t = threadIdx.x;
    int i0 = b * 1024 + t * 4;
    int v[4];
    int tot = 0;
#pragma unroll
    for (int j = 0; j < 4; j++) {
        int i = i0 + j;
        v[j] = (i < NN) ? degi[i] : 0;
        tot += v[j];
    }
    ss[t] = tot;
    __syncthreads();
#pragma unroll
    for (int o = 1; o < 256; o <<= 1) {
        int x = (t >= o) ? ss[t - o] : 0;
        __syncthreads();
        ss[t] += x;
        __syncthreads();
    }
    int run = boff[b] + ((t == 0) ? 0 : ss[t - 1]);
#pragma unroll
    for (int j = 0; j < 4; j++) {
        int i = i0 + j;
        if (i < NN) { off[i] = run; cur[i] = run; }
        run += v[j];
    }
}

__global__ void fill_kernel(const int* __restrict__ ei,
                            int* __restrict__ cur, int* __restrict__ csr) {
    int e = blockIdx.x * blockDim.x + threadIdx.x;
    if (e >= NE) return;
    int src = ei[e];
    int dst = ei[NE + e];
    int p = atomicAdd(&cur[dst], 1);
    csr[p] = src;
}

// ---------------------------------------------------------------------------
// Y = act( mean_gather(Xin) @ Wl.T + bl + Xin @ Wr.T )
// Phase 1: gather neighbor rows via CSR into sIn (mean), accumulate with Wl.
// Phase 2: load Xin tile, accumulate with Wr, epilogue.
// 256 threads, 128 rows x 64 cols, 8x4 thread tile, FFMA2, 52.2 KB smem -> 3/SM.
// ---------------------------------------------------------------------------
#define WPAD 68
#define RPB  128

__device__ __forceinline__ void accum_phase(const float* __restrict__ sW,
                                            const float* __restrict__ sIn,
                                            int h0, int r0, u64 acc[8][2]) {
#pragma unroll
    for (int k = 0; k < 64; k += 4) {
        ulonglong2 w[4];
#pragma unroll
        for (int kk = 0; kk < 4; kk++)
            w[kk] = *(const ulonglong2*)&sW[(k + kk) * WPAD + h0];
#pragma unroll
        for (int i = 0; i < 8; i++) {
            float4 v = *(const float4*)&sIn[(r0 + i) * WPAD + k];
            u64 t;
            t = bcast2(v.x); acc[i][0] = ffma2(t, w[0].x, acc[i][0]);
                             acc[i][1] = ffma2(t, w[0].y, acc[i][1]);
            t = bcast2(v.y); acc[i][0] = ffma2(t, w[1].x, acc[i][0]);
                             acc[i][1] = ffma2(t, w[1].y, acc[i][1]);
            t = bcast2(v.z); acc[i][0] = ffma2(t, w[2].x, acc[i][0]);
                             acc[i][1] = ffma2(t, w[2].y, acc[i][1]);
            t = bcast2(v.w); acc[i][0] = ffma2(t, w[3].x, acc[i][0]);
                             acc[i][1] = ffma2(t, w[3].y, acc[i][1]);
        }
    }
}

template <bool RELU>
__global__ void __launch_bounds__(256, 3)
combine_kernel(const float* __restrict__ Xin,
               const int* __restrict__ off, const int* __restrict__ csr,
               const float* __restrict__ Wl, const float* __restrict__ bl,
               const float* __restrict__ Wr, float* __restrict__ Y) {
    extern __shared__ float smem[];
    float* sW  = smem;               // [64][WPAD]
    float* sIn = smem + 64 * WPAD;   // [128][WPAD]
    __shared__ float sb[64];

    int tid  = threadIdx.x;
    int base = blockIdx.x * RPB;

    // phase-1 weights + bias
    for (int i = tid; i < 64 * 64; i += 256) {
        int h = i >> 6, k = i & 63;
        sW[k * WPAD + h] = Wl[i];
    }
    if (tid < 64) sb[tid] = bl[tid];

    // gather: 16 lanes per row (float4 each), 8 rows per 16-thread group
    int grp = tid >> 4;        // 0..15
    int l   = tid & 15;        // float4 index within row
#pragma unroll
    for (int g = 0; g < 8; g++) {
        int r   = grp * 8 + g;
        int row = base + r;
        float4 acc = make_float4(0.f, 0.f, 0.f, 0.f);
        if (row < NN) {
            int s0 = off[row], s1 = off[row + 1];
            int e = s0;
            for (; e + 1 < s1; e += 2) {   // 2-way for MLP
                int sa = csr[e], sbn = csr[e + 1];
                float4 va = *(const float4*)&Xin[(size_t)sa * HDIM + l * 4];
                float4 vb = *(const float4*)&Xin[(size_t)sbn * HDIM + l * 4];
                acc.x += va.x + vb.x; acc.y += va.y + vb.y;
                acc.z += va.z + vb.z; acc.w += va.w + vb.w;
            }
            if (e < s1) {
                int sa = csr[e];
                float4 va = *(const float4*)&Xin[(size_t)sa * HDIM + l * 4];
                acc.x += va.x; acc.y += va.y; acc.z += va.z; acc.w += va.w;
            }
            float inv = 1.f / fmaxf((float)(s1 - s0), 1.f);
            acc.x *= inv; acc.y *= inv; acc.z *= inv; acc.w *= inv;
        }
        *(float4*)&sIn[r * WPAD + l * 4] = acc;
    }
    __syncthreads();

    int h0 = (tid & 15) * 4;
    int r0 = (tid >> 4) * 8;

    u64 acc[8][2];
    {
        u64 b01 = pack2(sb[h0], sb[h0 + 1]);
        u64 b23 = pack2(sb[h0 + 2], sb[h0 + 3]);
#pragma unroll
        for (int i = 0; i < 8; i++) { acc[i][0] = b01; acc[i][1] = b23; }
    }

    accum_phase(sW, sIn, h0, r0, acc);      // mean @ Wl^T
    __syncthreads();

    // phase-2 loads: Wr^T + x tile
    for (int i = tid; i < 64 * 64; i += 256) {
        int h = i >> 6, k = i & 63;
        sW[k * WPAD + h] = Wr[i];
    }
    for (int i = tid; i < RPB * 16; i += 256) {
        int r = i >> 4, k4 = (i & 15) * 4;
        int row = base + r;
        float4 v = make_float4(0.f, 0.f, 0.f, 0.f);
        if (row < NN) v = *(const float4*)&Xin[(size_t)row * HDIM + k4];
        *(float4*)&sIn[r * WPAD + k4] = v;
    }
    __syncthreads();

    accum_phase(sW, sIn, h0, r0, acc);      // + x @ Wr^T

#pragma unroll
    for (int i = 0; i < 8; i++) {
        int row = base + r0 + i;
        if (row >= NN) break;
        float2 lo = unpack2(acc[i][0]);
        float2 hi = unpack2(acc[i][1]);
        float4 o;
        o.x = lo.x; o.y = lo.y; o.z = hi.x; o.w = hi.y;
        if (RELU) {
            o.x = fmaxf(o.x, 0.f); o.y = fmaxf(o.y, 0.f);
            o.z = fmaxf(o.z, 0.f); o.w = fmaxf(o.w, 0.f);
        }
        *(float4*)&Y[(size_t)row * HDIM + h0] = o;
    }
}

// ---------------------------------------------------------------------------
// out[e] = dot(Z[u[e]], Z[N_USERS + m[e]]) — 16 lanes per label edge, float4
// ---------------------------------------------------------------------------
__global__ void dot_kernel(const int* __restrict__ eli,
                           const float* __restrict__ Z,
                           float* __restrict__ out) {
    int gw = (blockIdx.x * blockDim.x + threadIdx.x) >> 4;
    int l  = threadIdx.x & 15;
    if (gw >= NEL) return;
    int u = __ldg(&eli[gw]);
    int m = __ldg(&eli[NEL + gw]);
    float4 a = *(const float4*)&Z[(size_t)u * HDIM + l * 4];
    float4 b = *(const float4*)&Z[(size_t)(N_USERS + m) * HDIM + l * 4];
    float s = a.x * b.x + a.y * b.y + a.z * b.z + a.w * b.w;
#pragma unroll
    for (int o = 8; o; o >>= 1) s += __shfl_xor_sync(0xffffffffu, s, o);
    if (l == 0) out[gw] = s;
}

// ---------------------------------------------------------------------------
extern "C" void kernel_launch(void* const* d_in, const int* in_sizes, int n_in,
                              void* d_out, int out_size) {
    const float* movie_x   = (const float*)d_in[0];
    const float* user_emb  = (const float*)d_in[1];
    const float* movie_emb = (const float*)d_in[2];
    const float* lin_W     = (const float*)d_in[3];
    const float* lin_b     = (const float*)d_in[4];
    const float* W1l       = (const float*)d_in[5];
    const float* b1        = (const float*)d_in[6];
    const float* W1r       = (const float*)d_in[7];
    const float* W2l       = (const float*)d_in[8];
    const float* b2        = (const float*)d_in[9];
    const float* W2r       = (const float*)d_in[10];
    const int*   ei        = (const int*)d_in[11];
    const int*   eli       = (const int*)d_in[12];
    float* out = (float*)d_out;

    float *dX, *dY, *dZ;
    int *dDEGI, *dOFF, *dCUR, *dBSUM, *dCSR;
    cudaGetSymbolAddress((void**)&dX,    g_X);
    cudaGetSymbolAddress((void**)&dY,    g_Y);
    cudaGetSymbolAddress((void**)&dZ,    g_Z);
    cudaGetSymbolAddress((void**)&dDEGI, g_DEGI);
    cudaGetSymbolAddress((void**)&dOFF,  g_OFF);
    cudaGetSymbolAddress((void**)&dCUR,  g_CUR);
    cudaGetSymbolAddress((void**)&dBSUM, g_BSUM);
    cudaGetSymbolAddress((void**)&dCSR,  g_CSR);

    const size_t smemC = (size_t)((64 + RPB) * WPAD) * sizeof(float); // 52.2 KB
    cudaFuncSetAttribute(combine_kernel<true>,
                         cudaFuncAttributeMaxDynamicSharedMemorySize, (int)smemC);
    cudaFuncSetAttribute(combine_kernel<false>,
                         cudaFuncAttributeMaxDynamicSharedMemorySize, (int)smemC);

    const int gridC = (NN + RPB - 1) / RPB;   // 2188

    // ---- node features + CSR build (independent work, one stream) ----
    cudaMemsetAsync(dDEGI, 0, NN * sizeof(int));
    init_X_kernel<<<(NN + 3) / 4, 256>>>(movie_x, user_emb, movie_emb,
                                         lin_W, lin_b, dX);
    hist_kernel<<<(NE + 255) / 256, 256>>>(ei, dDEGI);
    scanA_kernel<<<NB, 256>>>(dDEGI, dBSUM);
    scanB_kernel<<<1, 512>>>(dBSUM, dOFF);
    scanC_kernel<<<NB, 256>>>(dDEGI, dBSUM, dOFF, dCUR);
    fill_kernel<<<(NE + 255) / 256, 256>>>(ei, dCUR, dCSR);

    // ---- layer 1 ----
    combine_kernel<true><<<gridC, 256, smemC>>>(dX, dOFF, dCSR,
                                                W1l, b1, W1r, dY);
    // ---- layer 2 ----
    combine_kernel<false><<<gridC, 256, smemC>>>(dY, dOFF, dCSR,
                                                 W2l, b2, W2r, dZ);
    // ---- decode ----
    dot_kernel<<<(NEL * 16) / 256, 256>>>(eli, dZ, out);
}

// round 6
// speedup vs baseline: 1.7829x; 1.0142x over previous
#include <cuda_runtime.h>
#include <cstddef>

#define N_USERS 200000
#define N_MOVIES 80000
#define NN 280000
#define HDIM 64
#define F_MOVIE 20
#define NE 1250000
#define NEL 500000
#define NB 274            // ceil(NN / 1024)

typedef unsigned long long u64;

// Scratch (static device globals: allowed; runtime allocation is not).
__device__ __align__(16) float g_X[(size_t)NN * HDIM];
__device__ __align__(16) float g_Y[(size_t)NN * HDIM];
__device__ __align__(16) float g_Z[(size_t)NN * HDIM];
__device__ int g_DEGI[NN];
__device__ int g_OFF[NN + 1];
__device__ int g_CUR[NN];
__device__ int g_BSUM[512];
__device__ int g_CSR[NE];

// ---- packed f32x2 helpers (Blackwell FFMA2 path, PTX-only) -----------------
__device__ __forceinline__ u64 pack2(float lo, float hi) {
    u64 r; asm("mov.b64 %0, {%1, %2};" : "=l"(r) : "f"(lo), "f"(hi)); return r;
}
__device__ __forceinline__ u64 bcast2(float x) {
    u64 r; asm("mov.b64 %0, {%1, %1};" : "=l"(r) : "f"(x)); return r;
}
__device__ __forceinline__ u64 ffma2(u64 a, u64 b, u64 c) {
    u64 d; asm("fma.rn.f32x2 %0, %1, %2, %3;" : "=l"(d) : "l"(a), "l"(b), "l"(c));
    return d;
}
__device__ __forceinline__ float2 unpack2(u64 v) {
    float2 f; asm("mov.b64 {%0, %1}, %2;" : "=f"(f.x), "=f"(f.y) : "l"(v)); return f;
}

// ---------------------------------------------------------------------------
// X init: users = copy user_emb; movies = movie_x @ lin_W.T + lin_b + movie_emb
// ---------------------------------------------------------------------------
__global__ void init_X_kernel(const float* __restrict__ movie_x,
                              const float* __restrict__ user_emb,
                              const float* __restrict__ movie_emb,
                              const float* __restrict__ lin_W,
                              const float* __restrict__ lin_b,
                              float* __restrict__ X) {
    __shared__ float sx[4][F_MOVIE];
    int lr  = threadIdx.x >> 6;
    int h   = threadIdx.x & 63;
    int row = blockIdx.x * 4 + lr;
    int mrow = row - N_USERS;
    if (row < NN && mrow >= 0 && h < F_MOVIE)
        sx[lr][h] = movie_x[mrow * F_MOVIE + h];
    __syncthreads();
    if (row >= NN) return;
    if (mrow < 0) {
        X[(size_t)row * HDIM + h] = user_emb[(size_t)row * HDIM + h];
    } else {
        float acc = lin_b[h] + movie_emb[(size_t)mrow * HDIM + h];
#pragma unroll
        for (int f = 0; f < F_MOVIE; f++)
            acc += sx[lr][f] * lin_W[h * F_MOVIE + f];
        X[(size_t)row * HDIM + h] = acc;
    }
}

// ---------------------------------------------------------------------------
// CSR build: histogram -> block sums -> scan of sums -> local scan -> fill
// ---------------------------------------------------------------------------
__global__ void hist_kernel(const int* __restrict__ ei, int* __restrict__ degi) {
    int e = blockIdx.x * blockDim.x + threadIdx.x;
    if (e < NE) atomicAdd(&degi[ei[NE + e]], 1);
}

__global__ void scanA_kernel(const int* __restrict__ degi, int* __restrict__ bsum) {
    __shared__ int ws[8];
    int b = blockIdx.x, t = threadIdx.x;
    int i0 = b * 1024 + t * 4;
    int s = 0;
#pragma unroll
    for (int j = 0; j < 4; j++) { int i = i0 + j; s += (i < NN) ? degi[i] : 0; }
#pragma unroll
    for (int o = 16; o; o >>= 1) s += __shfl_xor_sync(0xffffffffu, s, o);
    if ((t & 31) == 0) ws[t >> 5] = s;
    __syncthreads();
    if (t == 0) {
        int tot = 0;
#pragma unroll
        for (int w = 0; w < 8; w++) tot += ws[w];
        bsum[b] = tot;
    }
}

__global__ void scanB_kernel(int* __restrict__ bsum, int* __restrict__ off) {
    __shared__ int s[512];
    int t = threadIdx.x;
    s[t] = (t < NB) ? bsum[t] : 0;
    __syncthreads();
#pragma unroll
    for (int o = 1; o < 512; o <<= 1) {
        int x = (t >= o) ? s[t - o] : 0;
        __syncthreads();
        s[t] += x;
        __syncthreads();
    }
    int excl = (t == 0) ? 0 : s[t - 1];
    if (t < NB) bsum[t] = excl;
    if (t == 0) off[NN] = NE;
}

__global__ void scanC_kernel(const int* __restrict__ degi,
                             const int* __restrict__ boff,
                             int* __restrict__ off, int* __restrict__ cur) {
    __shared__ int ss[256];
    int b = blockIdx.x, t = threadIdx.x;
    int i0 = b * 1024 + t * 4;
    int v[4];
    int tot = 0;
#pragma unroll
    for (int j = 0; j < 4; j++) {
        int i = i0 + j;
        v[j] = (i < NN) ? degi[i] : 0;
        tot += v[j];
    }
    ss[t] = tot;
    __syncthreads();
#pragma unroll
    for (int o = 1; o < 256; o <<= 1) {
        int x = (t >= o) ? ss[t - o] : 0;
        __syncthreads();
        ss[t] += x;
        __syncthreads();
    }
    int run = boff[b] + ((t == 0) ? 0 : ss[t - 1]);
#pragma unroll
    for (int j = 0; j < 4; j++) {
        int i = i0 + j;
        if (i < NN) { off[i] = run; cur[i] = run; }
        run += v[j];
    }
}

__global__ void fill_kernel(const int* __restrict__ ei,
                            int* __restrict__ cur, int* __restrict__ csr) {
    int e = blockIdx.x * blockDim.x + threadIdx.x;
    if (e >= NE) return;
    int src = ei[e];
    int dst = ei[NE + e];
    int p = atomicAdd(&cur[dst], 1);
    csr[p] = src;
}

// ---------------------------------------------------------------------------
// Y = act( mean_gather(Xin) @ Wl.T + bl + Xin @ Wr.T )
// Gather: warp-per-row-pair, 32 lanes x float2 cover a row; 2 rows x 2 edges
// per iteration -> 4 independent loads in flight, warp-uniform control flow.
// GEMM: 128x64 tile, 8x4 thread tile, FFMA2, phased weights (52.2 KB smem).
// ---------------------------------------------------------------------------
#define WPAD 68
#define RPB  128

__device__ __forceinline__ void accum_phase(const float* __restrict__ sW,
                                            const float* __restrict__ sIn,
                                            int h0, int r0, u64 acc[8][2]) {
#pragma unroll
    for (int k = 0; k < 64; k += 4) {
        ulonglong2 w[4];
#pragma unroll
        for (int kk = 0; kk < 4; kk++)
            w[kk] = *(const ulonglong2*)&sW[(k + kk) * WPAD + h0];
#pragma unroll
        for (int i = 0; i < 8; i++) {
            float4 v = *(const float4*)&sIn[(r0 + i) * WPAD + k];
            u64 t;
            t = bcast2(v.x); acc[i][0] = ffma2(t, w[0].x, acc[i][0]);
                             acc[i][1] = ffma2(t, w[0].y, acc[i][1]);
            t = bcast2(v.y); acc[i][0] = ffma2(t, w[1].x, acc[i][0]);
                             acc[i][1] = ffma2(t, w[1].y, acc[i][1]);
            t = bcast2(v.z); acc[i][0] = ffma2(t, w[2].x, acc[i][0]);
                             acc[i][1] = ffma2(t, w[2].y, acc[i][1]);
            t = bcast2(v.w); acc[i][0] = ffma2(t, w[3].x, acc[i][0]);
                             acc[i][1] = ffma2(t, w[3].y, acc[i][1]);
        }
    }
}

template <bool RELU>
__global__ void __launch_bounds__(256, 3)
combine_kernel(const float* __restrict__ Xin,
               const int* __restrict__ off, const int* __restrict__ csr,
               const float* __restrict__ Wl, const float* __restrict__ bl,
               const float* __restrict__ Wr, float* __restrict__ Y) {
    extern __shared__ float smem[];
    float* sW  = smem;               // [64][WPAD]
    float* sIn = smem + 64 * WPAD;   // [128][WPAD]
    __shared__ float sb[64];

    int tid  = threadIdx.x;
    int base = blockIdx.x * RPB;

    // phase-1 weights + bias
    for (int i = tid; i < 64 * 64; i += 256) {
        int h = i >> 6, k = i & 63;
        sW[k * WPAD + h] = Wl[i];
    }
    if (tid < 64) sb[tid] = bl[tid];

    // ---- gather: warp per row pair, float2 lanes ----
    {
        int wid  = tid >> 5;       // 0..7
        int lane = tid & 31;
#pragma unroll
        for (int p = 0; p < 8; p++) {
            int rA = wid * 16 + p * 2;     // local rows rA, rA+1
            int rowA = base + rA;
            int rowB = rowA + 1;
            int o0 = 0, o1 = 0, o2 = 0;
            if (rowA < NN) {
                o0 = __ldg(&off[rowA]);
                o1 = __ldg(&off[rowA + 1]);
                o2 = (rowB < NN) ? __ldg(&off[rowB + 1]) : o1;
            }
            int remA = o1 - o0, remB = o2 - o1;
            float2 accA = make_float2(0.f, 0.f);
            float2 accB = make_float2(0.f, 0.f);
            int eA = o0, eB = o1;
            int iters = max((remA + 1) >> 1, (remB + 1) >> 1);
            for (int it = 0; it < iters; it++) {
                // hoist index loads (warp-uniform)
                int iA0 = (eA     < o1) ? __ldg(&csr[eA])     : -1;
                int iA1 = (eA + 1 < o1) ? __ldg(&csr[eA + 1]) : -1;
                int iB0 = (eB     < o2) ? __ldg(&csr[eB])     : -1;
                int iB1 = (eB + 1 < o2) ? __ldg(&csr[eB + 1]) : -1;
                // 4 independent feature loads
                float2 vA0 = (iA0 >= 0) ? *(const float2*)&Xin[(size_t)iA0 * HDIM + lane * 2]
                                        : make_float2(0.f, 0.f);
                float2 vA1 = (iA1 >= 0) ? *(const float2*)&Xin[(size_t)iA1 * HDIM + lane * 2]
                                        : make_float2(0.f, 0.f);
                float2 vB0 = (iB0 >= 0) ? *(const float2*)&Xin[(size_t)iB0 * HDIM + lane * 2]
                                        : make_float2(0.f, 0.f);
                float2 vB1 = (iB1 >= 0) ? *(const float2*)&Xin[(size_t)iB1 * HDIM + lane * 2]
                                        : make_float2(0.f, 0.f);
                accA.x += vA0.x + vA1.x;  accA.y += vA0.y + vA1.y;
                accB.x += vB0.x + vB1.x;  accB.y += vB0.y + vB1.y;
                eA += 2; eB += 2;
            }
            float invA = 1.f / fmaxf((float)remA, 1.f);
            float invB = 1.f / fmaxf((float)remB, 1.f);
            accA.x *= invA; accA.y *= invA;
            accB.x *= invB; accB.y *= invB;
            *(float2*)&sIn[rA * WPAD + lane * 2]       = accA;
            *(float2*)&sIn[(rA + 1) * WPAD + lane * 2] = accB;
        }
    }
    __syncthreads();

    int h0 = (tid & 15) * 4;
    int r0 = (tid >> 4) * 8;

    u64 acc[8][2];
    {
        u64 b01 = pack2(sb[h0], sb[h0 + 1]);
        u64 b23 = pack2(sb[h0 + 2], sb[h0 + 3]);
#pragma unroll
        for (int i = 0; i < 8; i++) { acc[i][0] = b01; acc[i][1] = b23; }
    }

    accum_phase(sW, sIn, h0, r0, acc);      // mean @ Wl^T
    __syncthreads();

    // phase-2 loads: Wr^T + x tile
    for (int i = tid; i < 64 * 64; i += 256) {
        int h = i >> 6, k = i & 63;
        sW[k * WPAD + h] = Wr[i];
    }
    for (int i = tid; i < RPB * 16; i += 256) {
        int r = i >> 4, k4 = (i & 15) * 4;
        int row = base + r;
        float4 v = make_float4(0.f, 0.f, 0.f, 0.f);
        if (row < NN) v = *(const float4*)&Xin[(size_t)row * HDIM + k4];
        *(float4*)&sIn[r * WPAD + k4] = v;
    }
    __syncthreads();

    accum_phase(sW, sIn, h0, r0, acc);      // + x @ Wr^T

#pragma unroll
    for (int i = 0; i < 8; i++) {
        int row = base + r0 + i;
        if (row >= NN) break;
        float2 lo = unpack2(acc[i][0]);
        float2 hi = unpack2(acc[i][1]);
        float4 o;
        o.x = lo.x; o.y = lo.y; o.z = hi.x; o.w = hi.y;
        if (RELU) {
            o.x = fmaxf(o.x, 0.f); o.y = fmaxf(o.y, 0.f);
            o.z = fmaxf(o.z, 0.f); o.w = fmaxf(o.w, 0.f);
        }
        *(float4*)&Y[(size_t)row * HDIM + h0] = o;
    }
}

// ---------------------------------------------------------------------------
// out[e] = dot(Z[u[e]], Z[N_USERS + m[e]]) — 16 lanes per label edge, float4
// ---------------------------------------------------------------------------
__global__ void dot_kernel(const int* __restrict__ eli,
                           const float* __restrict__ Z,
                           float* __restrict__ out) {
    int gw = (blockIdx.x * blockDim.x + threadIdx.x) >> 4;
    int l  = threadIdx.x & 15;
    if (gw >= NEL) return;
    int u = __ldg(&eli[gw]);
    int m = __ldg(&eli[NEL + gw]);
    float4 a = *(const float4*)&Z[(size_t)u * HDIM + l * 4];
    float4 b = *(const float4*)&Z[(size_t)(N_USERS + m) * HDIM + l * 4];
    float s = a.x * b.x + a.y * b.y + a.z * b.z + a.w * b.w;
#pragma unroll
    for (int o = 8; o; o >>= 1) s += __shfl_xor_sync(0xffffffffu, s, o);
    if (l == 0) out[gw] = s;
}

// ---------------------------------------------------------------------------
extern "C" void kernel_launch(void* const* d_in, const int* in_sizes, int n_in,
                              void* d_out, int out_size) {
    const float* movie_x   = (const float*)d_in[0];
    const float* user_emb  = (const float*)d_in[1];
    const float* movie_emb = (const float*)d_in[2];
    const float* lin_W     = (const float*)d_in[3];
    const float* lin_b     = (const float*)d_in[4];
    const float* W1l       = (const float*)d_in[5];
    const float* b1        = (const float*)d_in[6];
    const float* W1r       = (const float*)d_in[7];
    const float* W2l       = (const float*)d_in[8];
    const float* b2        = (const float*)d_in[9];
    const float* W2r       = (const float*)d_in[10];
    const int*   ei        = (const int*)d_in[11];
    const int*   eli       = (const int*)d_in[12];
    float* out = (float*)d_out;

    float *dX, *dY, *dZ;
    int *dDEGI, *dOFF, *dCUR, *dBSUM, *dCSR;
    cudaGetSymbolAddress((void**)&dX,    g_X);
    cudaGetSymbolAddress((void**)&dY,    g_Y);
    cudaGetSymbolAddress((void**)&dZ,    g_Z);
    cudaGetSymbolAddress((void**)&dDEGI, g_DEGI);
    cudaGetSymbolAddress((void**)&dOFF,  g_OFF);
    cudaGetSymbolAddress((void**)&dCUR,  g_CUR);
    cudaGetSymbolAddress((void**)&dBSUM, g_BSUM);
    cudaGetSymbolAddress((void**)&dCSR,  g_CSR);

    const size_t smemC = (size_t)((64 + RPB) * WPAD) * sizeof(float); // 52.2 KB
    cudaFuncSetAttribute(combine_kernel<true>,
                         cudaFuncAttributeMaxDynamicSharedMemorySize, (int)smemC);
    cudaFuncSetAttribute(combine_kernel<false>,
                         cudaFuncAttributeMaxDynamicSharedMemorySize, (int)smemC);

    const int gridC = (NN + RPB - 1) / RPB;   // 2188

    // ---- node features + CSR build ----
    cudaMemsetAsync(dDEGI, 0, NN * sizeof(int));
    init_X_kernel<<<(NN + 3) / 4, 256>>>(movie_x, user_emb, movie_emb,
                                         lin_W, lin_b, dX);
    hist_kernel<<<(NE + 255) / 256, 256>>>(ei, dDEGI);
    scanA_kernel<<<NB, 256>>>(dDEGI, dBSUM);
    scanB_kernel<<<1, 512>>>(dBSUM, dOFF);
    scanC_kernel<<<NB, 256>>>(dDEGI, dBSUM, dOFF, dCUR);
    fill_kernel<<<(NE + 255) / 256, 256>>>(ei, dCUR, dCSR);

    // ---- layer 1 ----
    combine_kernel<true><<<gridC, 256, smemC>>>(dX, dOFF, dCSR,
                                                W1l, b1, W1r, dY);
    // ---- layer 2 ----
    combine_kernel<false><<<gridC, 256, smemC>>>(dY, dOFF, dCSR,
                                                 W2l, b2, W2r, dZ);
    // ---- decode ----
    dot_kernel<<<(NEL * 16) / 256, 256>>>(eli, dZ, out);
}

// round 7
// speedup vs baseline: 1.8095x; 1.0149x over previous
#include <cuda_runtime.h>
#include <cstddef>

#define N_USERS 200000
#define N_MOVIES 80000
#define NN 280000
#define HDIM 64
#define F_MOVIE 20
#define NE 1250000
#define NEL 500000
#define NB 274            // ceil(NN / 1024)

typedef unsigned long long u64;

// Scratch (static device globals: allowed; runtime allocation is not).
__device__ __align__(16) float g_X[(size_t)NN * HDIM];
__device__ __align__(16) float g_Y[(size_t)NN * HDIM];
__device__ __align__(16) float g_Z[(size_t)NN * HDIM];
__device__ __align__(16) float g_M[(size_t)NN * HDIM];
__device__ int g_DEGI[NN];
__device__ int g_OFF[NN + 1];
__device__ int g_CUR[NN];
__device__ int g_BSUM[512];
__device__ int g_CSR[NE];

// ---- packed f32x2 helpers (Blackwell FFMA2 path, PTX-only) -----------------
__device__ __forceinline__ u64 pack2(float lo, float hi) {
    u64 r; asm("mov.b64 %0, {%1, %2};" : "=l"(r) : "f"(lo), "f"(hi)); return r;
}
__device__ __forceinline__ u64 bcast2(float x) {
    u64 r; asm("mov.b64 %0, {%1, %1};" : "=l"(r) : "f"(x)); return r;
}
__device__ __forceinline__ u64 ffma2(u64 a, u64 b, u64 c) {
    u64 d; asm("fma.rn.f32x2 %0, %1, %2, %3;" : "=l"(d) : "l"(a), "l"(b), "l"(c));
    return d;
}
__device__ __forceinline__ float2 unpack2(u64 v) {
    float2 f; asm("mov.b64 {%0, %1}, %2;" : "=f"(f.x), "=f"(f.y) : "l"(v)); return f;
}

// ---------------------------------------------------------------------------
// X init: users = copy user_emb; movies = movie_x @ lin_W.T + lin_b + movie_emb
// ---------------------------------------------------------------------------
__global__ void init_X_kernel(const float* __restrict__ movie_x,
                              const float* __restrict__ user_emb,
                              const float* __restrict__ movie_emb,
                              const float* __restrict__ lin_W,
                              const float* __restrict__ lin_b,
                              float* __restrict__ X) {
    __shared__ float sx[4][F_MOVIE];
    int lr  = threadIdx.x >> 6;
    int h   = threadIdx.x & 63;
    int row = blockIdx.x * 4 + lr;
    int mrow = row - N_USERS;
    if (row < NN && mrow >= 0 && h < F_MOVIE)
        sx[lr][h] = movie_x[mrow * F_MOVIE + h];
    __syncthreads();
    if (row >= NN) return;
    if (mrow < 0) {
        X[(size_t)row * HDIM + h] = user_emb[(size_t)row * HDIM + h];
    } else {
        float acc = lin_b[h] + movie_emb[(size_t)mrow * HDIM + h];
#pragma unroll
        for (int f = 0; f < F_MOVIE; f++)
            acc += sx[lr][f] * lin_W[h * F_MOVIE + f];
        X[(size_t)row * HDIM + h] = acc;
    }
}

// ---------------------------------------------------------------------------
// CSR build: histogram -> block sums -> scan of sums -> local scan -> fill
// ---------------------------------------------------------------------------
__global__ void hist_kernel(const int* __restrict__ ei, int* __restrict__ degi) {
    int e = blockIdx.x * blockDim.x + threadIdx.x;
    if (e < NE) atomicAdd(&degi[ei[NE + e]], 1);
}

__global__ void scanA_kernel(const int* __restrict__ degi, int* __restrict__ bsum) {
    __shared__ int ws[8];
    int b = blockIdx.x, t = threadIdx.x;
    int i0 = b * 1024 + t * 4;
    int s = 0;
#pragma unroll
    for (int j = 0; j < 4; j++) { int i = i0 + j; s += (i < NN) ? degi[i] : 0; }
#pragma unroll
    for (int o = 16; o; o >>= 1) s += __shfl_xor_sync(0xffffffffu, s, o);
    if ((t & 31) == 0) ws[t >> 5] = s;
    __syncthreads();
    if (t == 0) {
        int tot = 0;
#pragma unroll
        for (int w = 0; w < 8; w++) tot += ws[w];
        bsum[b] = tot;
    }
}

__global__ void scanB_kernel(int* __restrict__ bsum, int* __restrict__ off) {
    __shared__ int s[512];
    int t = threadIdx.x;
    s[t] = (t < NB) ? bsum[t] : 0;
    __syncthreads();
#pragma unroll
    for (int o = 1; o < 512; o <<= 1) {
        int x = (t >= o) ? s[t - o] : 0;
        __syncthreads();
        s[t] += x;
        __syncthreads();
    }
    int excl = (t == 0) ? 0 : s[t - 1];
    if (t < NB) bsum[t] = excl;
    if (t == 0) off[NN] = NE;
}

__global__ void scanC_kernel(const int* __restrict__ degi,
                             const int* __restrict__ boff,
                             int* __restrict__ off, int* __restrict__ cur) {
    __shared__ int ss[256];
    int b = blockIdx.x, t = threadIdx.x;
    int i0 = b * 1024 + t * 4;
    int v[4];
    int tot = 0;
#pragma unroll
    for (int j = 0; j < 4; j++) {
        int i = i0 + j;
        v[j] = (i < NN) ? degi[i] : 0;
        tot += v[j];
    }
    ss[t] = tot;
    __syncthreads();
#pragma unroll
    for (int o = 1; o < 256; o <<= 1) {
        int x = (t >= o) ? ss[t - o] : 0;
        __syncthreads();
        ss[t] += x;
        __syncthreads();
    }
    int run = boff[b] + ((t == 0) ? 0 : ss[t - 1]);
#pragma unroll
    for (int j = 0; j < 4; j++) {
        int i = i0 + j;
        if (i < NN) { off[i] = run; cur[i] = run; }
        run += v[j];
    }
}

__global__ void fill_kernel(const int* __restrict__ ei,
                            int* __restrict__ cur, int* __restrict__ csr) {
    int e = blockIdx.x * blockDim.x + threadIdx.x;
    if (e >= NE) return;
    int src = ei[e];
    int dst = ei[NE + e];
    int p = atomicAdd(&cur[dst], 1);
    csr[p] = src;
}

// ---------------------------------------------------------------------------
// MEAN[row] = mean over neighbors of Xin[src] — warp per row, float2 lanes,
// 4 predicated loads per iteration (MLP=4 even on the tail). No smem ->
// near-full occupancy; latency-bound part runs at 64 warps/SM.
// ---------------------------------------------------------------------------
__global__ void __launch_bounds__(256)
gather_kernel(const float* __restrict__ Xin,
              const int* __restrict__ off, const int* __restrict__ csr,
              float* __restrict__ MEAN) {
    int row  = (blockIdx.x * blockDim.x + threadIdx.x) >> 5;
    int lane = threadIdx.x & 31;
    if (row >= NN) return;
    int s0 = __ldg(&off[row]);
    int s1 = __ldg(&off[row + 1]);
    float2 acc = make_float2(0.f, 0.f);
    for (int e = s0; e < s1; e += 4) {
        int i0 = (e     < s1) ? __ldg(&csr[e])     : -1;
        int i1 = (e + 1 < s1) ? __ldg(&csr[e + 1]) : -1;
        int i2 = (e + 2 < s1) ? __ldg(&csr[e + 2]) : -1;
        int i3 = (e + 3 < s1) ? __ldg(&csr[e + 3]) : -1;
        float2 v0 = (i0 >= 0) ? *(const float2*)&Xin[(size_t)i0 * HDIM + lane * 2]
                              : make_float2(0.f, 0.f);
        float2 v1 = (i1 >= 0) ? *(const float2*)&Xin[(size_t)i1 * HDIM + lane * 2]
                              : make_float2(0.f, 0.f);
        float2 v2 = (i2 >= 0) ? *(const float2*)&Xin[(size_t)i2 * HDIM + lane * 2]
                              : make_float2(0.f, 0.f);
        float2 v3 = (i3 >= 0) ? *(const float2*)&Xin[(size_t)i3 * HDIM + lane * 2]
                              : make_float2(0.f, 0.f);
        acc.x += (v0.x + v1.x) + (v2.x + v3.x);
        acc.y += (v0.y + v1.y) + (v2.y + v3.y);
    }
    float inv = 1.f / fmaxf((float)(s1 - s0), 1.f);
    acc.x *= inv; acc.y *= inv;
    *(float2*)&MEAN[(size_t)row * HDIM + lane * 2] = acc;
}

// ---------------------------------------------------------------------------
// Y = act( MEAN @ Wl.T + bl + Xin @ Wr.T )  — pure GEMM, phased weights.
// 256 threads, 128x64 tile, 8x4 thread tile, FFMA2.
// 52.2 KB dynamic smem, __launch_bounds__(256,4) -> 4 blocks/SM (32 warps).
// ---------------------------------------------------------------------------
#define WPAD 68
#define RPB  128

__device__ __forceinline__ void accum_phase(const float* __restrict__ sW,
                                            const float* __restrict__ sIn,
                                            int h0, int r0, u64 acc[8][2]) {
#pragma unroll
    for (int k = 0; k < 64; k += 4) {
        ulonglong2 w[4];
#pragma unroll
        for (int kk = 0; kk < 4; kk++)
            w[kk] = *(const ulonglong2*)&sW[(k + kk) * WPAD + h0];
#pragma unroll
        for (int i = 0; i < 8; i++) {
            float4 v = *(const float4*)&sIn[(r0 + i) * WPAD + k];
            u64 t;
            t = bcast2(v.x); acc[i][0] = ffma2(t, w[0].x, acc[i][0]);
                             acc[i][1] = ffma2(t, w[0].y, acc[i][1]);
            t = bcast2(v.y); acc[i][0] = ffma2(t, w[1].x, acc[i][0]);
                             acc[i][1] = ffma2(t, w[1].y, acc[i][1]);
            t = bcast2(v.z); acc[i][0] = ffma2(t, w[2].x, acc[i][0]);
                             acc[i][1] = ffma2(t, w[2].y, acc[i][1]);
            t = bcast2(v.w); acc[i][0] = ffma2(t, w[3].x, acc[i][0]);
                             acc[i][1] = ffma2(t, w[3].y, acc[i][1]);
        }
    }
}

template <bool RELU>
__global__ void __launch_bounds__(256, 4)
combine_kernel(const float* __restrict__ Xin, const float* __restrict__ MEAN,
               const float* __restrict__ Wl, const float* __restrict__ bl,
               const float* __restrict__ Wr, float* __restrict__ Y) {
    extern __shared__ float smem[];
    float* sW  = smem;               // [64][WPAD]
    float* sIn = smem + 64 * WPAD;   // [128][WPAD]
    __shared__ float sb[64];

    int tid  = threadIdx.x;
    int base = blockIdx.x * RPB;

    // phase-1: Wl^T + MEAN tile
    for (int i = tid; i < 64 * 64; i += 256) {
        int h = i >> 6, k = i & 63;
        sW[k * WPAD + h] = Wl[i];
    }
    if (tid < 64) sb[tid] = bl[tid];
    for (int i = tid; i < RPB * 16; i += 256) {
        int r = i >> 4, k4 = (i & 15) * 4;
        int row = base + r;
        float4 v = make_float4(0.f, 0.f, 0.f, 0.f);
        if (row < NN) v = *(const float4*)&MEAN[(size_t)row * HDIM + k4];
        *(float4*)&sIn[r * WPAD + k4] = v;
    }
    __syncthreads();

    int h0 = (tid & 15) * 4;
    int r0 = (tid >> 4) * 8;

    u64 acc[8][2];
    {
        u64 b01 = pack2(sb[h0], sb[h0 + 1]);
        u64 b23 = pack2(sb[h0 + 2], sb[h0 + 3]);
#pragma unroll
        for (int i = 0; i < 8; i++) { acc[i][0] = b01; acc[i][1] = b23; }
    }

    accum_phase(sW, sIn, h0, r0, acc);      // mean @ Wl^T
    __syncthreads();

    // phase-2: Wr^T + x tile
    for (int i = tid; i < 64 * 64; i += 256) {
        int h = i >> 6, k = i & 63;
        sW[k * WPAD + h] = Wr[i];
    }
    for (int i = tid; i < RPB * 16; i += 256) {
        int r = i >> 4, k4 = (i & 15) * 4;
        int row = base + r;
        float4 v = make_float4(0.f, 0.f, 0.f, 0.f);
        if (row < NN) v = *(const float4*)&Xin[(size_t)row * HDIM + k4];
        *(float4*)&sIn[r * WPAD + k4] = v;
    }
    __syncthreads();

    accum_phase(sW, sIn, h0, r0, acc);      // + x @ Wr^T

#pragma unroll
    for (int i = 0; i < 8; i++) {
        int row = base + r0 + i;
        if (row >= NN) break;
        float2 lo = unpack2(acc[i][0]);
        float2 hi = unpack2(acc[i][1]);
        float4 o;
        o.x = lo.x; o.y = lo.y; o.z = hi.x; o.w = hi.y;
        if (RELU) {
            o.x = fmaxf(o.x, 0.f); o.y = fmaxf(o.y, 0.f);
            o.z = fmaxf(o.z, 0.f); o.w = fmaxf(o.w, 0.f);
        }
        *(float4*)&Y[(size_t)row * HDIM + h0] = o;
    }
}

// ---------------------------------------------------------------------------
// out[e] = dot(Z[u[e]], Z[N_USERS + m[e]]) — 16 lanes per label edge, float4
// ---------------------------------------------------------------------------
__global__ void dot_kernel(const int* __restrict__ eli,
                           const float* __restrict__ Z,
                           float* __restrict__ out) {
    int gw = (blockIdx.x * blockDim.x + threadIdx.x) >> 4;
    int l  = threadIdx.x & 15;
    if (gw >= NEL) return;
    int u = __ldg(&eli[gw]);
    int m = __ldg(&eli[NEL + gw]);
    float4 a = *(const float4*)&Z[(size_t)u * HDIM + l * 4];
    float4 b = *(const float4*)&Z[(size_t)(N_USERS + m) * HDIM + l * 4];
    float s = a.x * b.x + a.y * b.y + a.z * b.z + a.w * b.w;
#pragma unroll
    for (int o = 8; o; o >>= 1) s += __shfl_xor_sync(0xffffffffu, s, o);
    if (l == 0) out[gw] = s;
}

// ---------------------------------------------------------------------------
extern "C" void kernel_launch(void* const* d_in, const int* in_sizes, int n_in,
                              void* d_out, int out_size) {
    const float* movie_x   = (const float*)d_in[0];
    const float* user_emb  = (const float*)d_in[1];
    const float* movie_emb = (const float*)d_in[2];
    const float* lin_W     = (const float*)d_in[3];
    const float* lin_b     = (const float*)d_in[4];
    const float* W1l       = (const float*)d_in[5];
    const float* b1        = (const float*)d_in[6];
    const float* W1r       = (const float*)d_in[7];
    const float* W2l       = (const float*)d_in[8];
    const float* b2        = (const float*)d_in[9];
    const float* W2r       = (const float*)d_in[10];
    const int*   ei        = (const int*)d_in[11];
    const int*   eli       = (const int*)d_in[12];
    float* out = (float*)d_out;

    float *dX, *dY, *dZ, *dM;
    int *dDEGI, *dOFF, *dCUR, *dBSUM, *dCSR;
    cudaGetSymbolAddress((void**)&dX,    g_X);
    cudaGetSymbolAddress((void**)&dY,    g_Y);
    cudaGetSymbolAddress((void**)&dZ,    g_Z);
    cudaGetSymbolAddress((void**)&dM,    g_M);
    cudaGetSymbolAddress((void**)&dDEGI, g_DEGI);
    cudaGetSymbolAddress((void**)&dOFF,  g_OFF);
    cudaGetSymbolAddress((void**)&dCUR,  g_CUR);
    cudaGetSymbolAddress((void**)&dBSUM, g_BSUM);
    cudaGetSymbolAddress((void**)&dCSR,  g_CSR);

    const size_t smemC = (size_t)((64 + RPB) * WPAD) * sizeof(float); // 52.2 KB
    cudaFuncSetAttribute(combine_kernel<true>,
                         cudaFuncAttributeMaxDynamicSharedMemorySize, (int)smemC);
    cudaFuncSetAttribute(combine_kernel<false>,
                         cudaFuncAttributeMaxDynamicSharedMemorySize, (int)smemC);

    const int gridC = (NN + RPB - 1) / RPB;   // 2188
    const int gridG = (NN * 32 + 255) / 256;  // warp per row

    // ---- node features + CSR build ----
    cudaMemsetAsync(dDEGI, 0, NN * sizeof(int));
    init_X_kernel<<<(NN + 3) / 4, 256>>>(movie_x, user_emb, movie_emb,
                                         lin_W, lin_b, dX);
    hist_kernel<<<(NE + 255) / 256, 256>>>(ei, dDEGI);
    scanA_kernel<<<NB, 256>>>(dDEGI, dBSUM);
    scanB_kernel<<<1, 512>>>(dBSUM, dOFF);
    scanC_kernel<<<NB, 256>>>(dDEGI, dBSUM, dOFF, dCUR);
    fill_kernel<<<(NE + 255) / 256, 256>>>(ei, dCUR, dCSR);

    // ---- layer 1 ----
    gather_kernel<<<gridG, 256>>>(dX, dOFF, dCSR, dM);
    combine_kernel<true><<<gridC, 256, smemC>>>(dX, dM, W1l, b1, W1r, dY);

    // ---- layer 2 ----
    gather_kernel<<<gridG, 256>>>(dY, dOFF, dCSR, dM);
    combine_kernel<false><<<gridC, 256, smemC>>>(dY, dM, W2l, b2, W2r, dZ);

    // ---- decode ----
    dot_kernel<<<(NEL * 16) / 256, 256>>>(eli, dZ, out);
}